// round 1
// baseline (speedup 1.0000x reference)
#include <cuda_runtime.h>
#include <cuda_bf16.h>

// Haar 3D wavelet (2x2x2, stride 2, causal temporal replicate-pad).
// x: (2,3,33,512,512) fp32 -> out: (2,24,17,256,256) fp32
// Channel layout: out[b, f*3 + c, t, h, w], f = filter index with bits
// (t_flip, h_flip, w_flip) = (f>>2, f>>1&1, f&1); value = SCALE * signed sum.

#define HAAR_SCALE 0.3536f

#define IN_T   33
#define IN_H   512
#define IN_W   512
#define OUT_T  17
#define OUT_H  256
#define OUT_W  256
#define NBC    6            // b*c = 2*3
#define WP     128          // output-column pairs per row (256/2)

__global__ __launch_bounds__(256)
void haar3d_kernel(const float* __restrict__ x, float* __restrict__ out)
{
    const int idx = blockIdx.x * 256 + threadIdx.x;
    // idx -> (bc, t, h, wp); wp fastest for coalescing
    const int wp   = idx & (WP - 1);          // 0..127
    const int h    = (idx >> 7) & (OUT_H - 1); // 0..255
    const int rest = idx >> 15;               // t + OUT_T*bc
    const int t    = rest % OUT_T;
    const int bc   = rest / OUT_T;
    if (bc >= NBC) return;

    const size_t IN_FRAME = (size_t)IN_H * IN_W;      // 262144
    const int t1 = 2 * t;                             // current frame
    const int t0 = (t1 - 1 < 0) ? 0 : (t1 - 1);       // causal replicate pad
    const int hh = 2 * h;
    const size_t col = (size_t)wp * 4;                // 4 input floats = 2 out cols

    const float* bx = x + (size_t)bc * IN_T * IN_FRAME;
    const float4 r00 = *(const float4*)(bx + (size_t)t0 * IN_FRAME + (size_t)(hh    ) * IN_W + col);
    const float4 r01 = *(const float4*)(bx + (size_t)t0 * IN_FRAME + (size_t)(hh + 1) * IN_W + col);
    const float4 r10 = *(const float4*)(bx + (size_t)t1 * IN_FRAME + (size_t)(hh    ) * IN_W + col);
    const float4 r11 = *(const float4*)(bx + (size_t)t1 * IN_FRAME + (size_t)(hh + 1) * IN_W + col);

    float2 o[8];

    #pragma unroll
    for (int k = 0; k < 2; k++) {
        // k=0 -> (.x,.y) pair, k=1 -> (.z,.w) pair
        const float v000 = k ? r00.z : r00.x;  // t-,h0,w0
        const float v001 = k ? r00.w : r00.y;  // t-,h0,w1
        const float v010 = k ? r01.z : r01.x;  // t-,h1,w0
        const float v011 = k ? r01.w : r01.y;  // t-,h1,w1
        const float v100 = k ? r10.z : r10.x;  // t ,h0,w0
        const float v101 = k ? r10.w : r10.y;
        const float v110 = k ? r11.z : r11.x;
        const float v111 = k ? r11.w : r11.y;

        // stage 1: along w
        const float a0 = v000 + v001, a1 = v000 - v001;
        const float a2 = v010 + v011, a3 = v010 - v011;
        const float a4 = v100 + v101, a5 = v100 - v101;
        const float a6 = v110 + v111, a7 = v110 - v111;
        // stage 2: along h
        const float b0 = a0 + a2, b1 = a1 + a3, b2 = a0 - a2, b3 = a1 - a3;
        const float b4 = a4 + a6, b5 = a5 + a7, b6 = a4 - a6, b7 = a5 - a7;
        // stage 3: along t; filter f bits = (t_flip<<2)|(h_flip<<1)|w_flip
        float r[8];
        r[0] = (b0 + b4) * HAAR_SCALE;  // 000
        r[1] = (b1 + b5) * HAAR_SCALE;  // 001 w
        r[2] = (b2 + b6) * HAAR_SCALE;  // 010 h
        r[3] = (b3 + b7) * HAAR_SCALE;  // 011 hw
        r[4] = (b0 - b4) * HAAR_SCALE;  // 100 t
        r[5] = (b1 - b5) * HAAR_SCALE;  // 101 tw
        r[6] = (b2 - b6) * HAAR_SCALE;  // 110 th
        r[7] = (b3 - b7) * HAAR_SCALE;  // 111 thw
        #pragma unroll
        for (int f = 0; f < 8; f++) {
            if (k == 0) o[f].x = r[f]; else o[f].y = r[f];
        }
    }

    const int  b  = bc / 3;
    const int  c  = bc - 3 * b;
    const size_t OUT_FRAME = (size_t)OUT_H * OUT_W;   // 65536
    const size_t spatial = (size_t)t * OUT_FRAME + (size_t)h * OUT_W + (size_t)wp * 2;

    #pragma unroll
    for (int f = 0; f < 8; f++) {
        const size_t ch = (size_t)(b * 24 + f * 3 + c);
        *(float2*)(out + ch * OUT_T * OUT_FRAME + spatial) = o[f];
    }
}

extern "C" void kernel_launch(void* const* d_in, const int* in_sizes, int n_in,
                              void* d_out, int out_size)
{
    const float* x = (const float*)d_in[0];
    float* out = (float*)d_out;
    // total threads = NBC * OUT_T * OUT_H * WP = 6*17*256*128 = 3,342,336
    const int total = NBC * OUT_T * OUT_H * WP;
    const int blocks = (total + 255) / 256;
    haar3d_kernel<<<blocks, 256>>>(x, out);
}

// round 2
// speedup vs baseline: 1.0019x; 1.0019x over previous
#include <cuda_runtime.h>
#include <cuda_bf16.h>

// Haar 3D wavelet (2x2x2, stride 2, causal temporal replicate-pad).
// x: (2,3,33,512,512) fp32 -> out: (2,24,17,256,256) fp32
// Channel layout: out[b, f*3 + c, t, h, w], f bits = (t_flip<<2)|(h_flip<<1)|w_flip.
// R1 -> R2: 4 output cols/thread (8x LDG.128 front-batched, 8x STG.128),
// streaming cache hints (__ldcs/__stcs).

#define HAAR_SCALE 0.3536f

#define IN_T   33
#define IN_H   512
#define IN_W   512
#define OUT_T  17
#define OUT_H  256
#define OUT_W  256
#define NBC    6            // b*c = 2*3
#define WQ     64           // output-column quads per row (256/4)

__global__ __launch_bounds__(256)
void haar3d_kernel(const float* __restrict__ x, float* __restrict__ out)
{
    const int idx = blockIdx.x * 256 + threadIdx.x;
    // idx -> (bc, t, h, wq); wq fastest for coalescing
    const int wq   = idx & (WQ - 1);            // 0..63
    const int h    = (idx >> 6) & (OUT_H - 1);  // 0..255
    const int rest = idx >> 14;                 // t + OUT_T*bc
    const int t    = rest % OUT_T;
    const int bc   = rest / OUT_T;
    if (bc >= NBC) return;

    const size_t IN_FRAME = (size_t)IN_H * IN_W;      // 262144
    const int t1 = 2 * t;                             // current frame
    const int t0 = (t1 - 1 < 0) ? 0 : (t1 - 1);       // causal replicate pad
    const int hh = 2 * h;
    const size_t col = (size_t)wq * 8;                // 8 input floats = 4 out cols

    const float* bx  = x + (size_t)bc * IN_T * IN_FRAME;
    const float* p00 = bx + (size_t)t0 * IN_FRAME + (size_t)(hh    ) * IN_W + col;
    const float* p01 = bx + (size_t)t0 * IN_FRAME + (size_t)(hh + 1) * IN_W + col;
    const float* p10 = bx + (size_t)t1 * IN_FRAME + (size_t)(hh    ) * IN_W + col;
    const float* p11 = bx + (size_t)t1 * IN_FRAME + (size_t)(hh + 1) * IN_W + col;

    // Front-batched loads: 8 x LDG.128 (128 B MLP per thread)
    const float4 a00 = __ldcs((const float4*)(p00));
    const float4 b00 = __ldcs((const float4*)(p00 + 4));
    const float4 a01 = __ldcs((const float4*)(p01));
    const float4 b01 = __ldcs((const float4*)(p01 + 4));
    const float4 a10 = __ldcs((const float4*)(p10));
    const float4 b10 = __ldcs((const float4*)(p10 + 4));
    const float4 a11 = __ldcs((const float4*)(p11));
    const float4 b11 = __ldcs((const float4*)(p11 + 4));

    // Repack into per-quad arrays: quad k uses input cols 2k, 2k+1
    const float w00[8] = {a00.x, a00.y, a00.z, a00.w, b00.x, b00.y, b00.z, b00.w};
    const float w01[8] = {a01.x, a01.y, a01.z, a01.w, b01.x, b01.y, b01.z, b01.w};
    const float w10[8] = {a10.x, a10.y, a10.z, a10.w, b10.x, b10.y, b10.z, b10.w};
    const float w11[8] = {a11.x, a11.y, a11.z, a11.w, b11.x, b11.y, b11.z, b11.w};

    float o[8][4];

    #pragma unroll
    for (int k = 0; k < 4; k++) {
        const float v000 = w00[2*k], v001 = w00[2*k+1];  // t-,h0
        const float v010 = w01[2*k], v011 = w01[2*k+1];  // t-,h1
        const float v100 = w10[2*k], v101 = w10[2*k+1];  // t ,h0
        const float v110 = w11[2*k], v111 = w11[2*k+1];  // t ,h1

        // stage 1: along w
        const float s0 = v000 + v001, s1 = v000 - v001;
        const float s2 = v010 + v011, s3 = v010 - v011;
        const float s4 = v100 + v101, s5 = v100 - v101;
        const float s6 = v110 + v111, s7 = v110 - v111;
        // stage 2: along h
        const float u0 = s0 + s2, u1 = s1 + s3, u2 = s0 - s2, u3 = s1 - s3;
        const float u4 = s4 + s6, u5 = s5 + s7, u6 = s4 - s6, u7 = s5 - s7;
        // stage 3: along t
        o[0][k] = (u0 + u4) * HAAR_SCALE;  // 000
        o[1][k] = (u1 + u5) * HAAR_SCALE;  // 001 w
        o[2][k] = (u2 + u6) * HAAR_SCALE;  // 010 h
        o[3][k] = (u3 + u7) * HAAR_SCALE;  // 011 hw
        o[4][k] = (u0 - u4) * HAAR_SCALE;  // 100 t
        o[5][k] = (u1 - u5) * HAAR_SCALE;  // 101 tw
        o[6][k] = (u2 - u6) * HAAR_SCALE;  // 110 th
        o[7][k] = (u3 - u7) * HAAR_SCALE;  // 111 thw
    }

    const int  b  = bc / 3;
    const int  c  = bc - 3 * b;
    const size_t OUT_FRAME = (size_t)OUT_H * OUT_W;   // 65536
    const size_t spatial = (size_t)t * OUT_FRAME + (size_t)h * OUT_W + (size_t)wq * 4;

    #pragma unroll
    for (int f = 0; f < 8; f++) {
        const size_t ch = (size_t)(b * 24 + f * 3 + c);
        float4 v = make_float4(o[f][0], o[f][1], o[f][2], o[f][3]);
        __stcs((float4*)(out + ch * OUT_T * OUT_FRAME + spatial), v);
    }
}

extern "C" void kernel_launch(void* const* d_in, const int* in_sizes, int n_in,
                              void* d_out, int out_size)
{
    const float* x = (const float*)d_in[0];
    float* out = (float*)d_out;
    // total threads = NBC * OUT_T * OUT_H * WQ = 6*17*256*64 = 1,671,168
    const int total = NBC * OUT_T * OUT_H * WQ;
    const int blocks = (total + 255) / 256;
    haar3d_kernel<<<blocks, 256>>>(x, out);
}

// round 3
// speedup vs baseline: 1.0078x; 1.0059x over previous
#include <cuda_runtime.h>
#include <cuda_bf16.h>

// Haar 3D wavelet (2x2x2, stride 2, causal temporal replicate-pad).
// x: (2,3,33,512,512) fp32 -> out: (2,24,17,256,256) fp32
// Channel layout: out[b, f*3 + c, t, h, w], f bits = (t_flip<<2)|(h_flip<<1)|w_flip.
// R3: R1 structure (2 cols/thread, 4x LDG.128, 8x STG.64) + 512-thread blocks,
// __ldcg single-use loads (L2-only), __stcs streaming stores.

#define HAAR_SCALE 0.3536f

#define IN_T   33
#define IN_H   512
#define IN_W   512
#define OUT_T  17
#define OUT_H  256
#define OUT_W  256
#define NBC    6            // b*c = 2*3
#define WP     128          // output-column pairs per row (256/2)
#define TPB    512

__global__ __launch_bounds__(TPB)
void haar3d_kernel(const float* __restrict__ x, float* __restrict__ out)
{
    const int idx = blockIdx.x * TPB + threadIdx.x;
    // idx -> (bc, t, h, wp); wp fastest for coalescing
    const int wp   = idx & (WP - 1);           // 0..127
    const int h    = (idx >> 7) & (OUT_H - 1); // 0..255
    const int rest = idx >> 15;                // t + OUT_T*bc
    const int t    = rest % OUT_T;
    const int bc   = rest / OUT_T;
    if (bc >= NBC) return;

    const size_t IN_FRAME = (size_t)IN_H * IN_W;      // 262144
    const int t1 = 2 * t;                             // current frame
    const int t0 = (t1 - 1 < 0) ? 0 : (t1 - 1);       // causal replicate pad
    const int hh = 2 * h;
    const size_t col = (size_t)wp * 4;                // 4 input floats = 2 out cols

    const float* bx = x + (size_t)bc * IN_T * IN_FRAME;
    const float4 r00 = __ldcg((const float4*)(bx + (size_t)t0 * IN_FRAME + (size_t)(hh    ) * IN_W + col));
    const float4 r01 = __ldcg((const float4*)(bx + (size_t)t0 * IN_FRAME + (size_t)(hh + 1) * IN_W + col));
    const float4 r10 = __ldcg((const float4*)(bx + (size_t)t1 * IN_FRAME + (size_t)(hh    ) * IN_W + col));
    const float4 r11 = __ldcg((const float4*)(bx + (size_t)t1 * IN_FRAME + (size_t)(hh + 1) * IN_W + col));

    float2 o[8];

    #pragma unroll
    for (int k = 0; k < 2; k++) {
        // k=0 -> (.x,.y) pair, k=1 -> (.z,.w) pair
        const float v000 = k ? r00.z : r00.x;  // t-,h0,w0
        const float v001 = k ? r00.w : r00.y;  // t-,h0,w1
        const float v010 = k ? r01.z : r01.x;  // t-,h1,w0
        const float v011 = k ? r01.w : r01.y;  // t-,h1,w1
        const float v100 = k ? r10.z : r10.x;  // t ,h0,w0
        const float v101 = k ? r10.w : r10.y;
        const float v110 = k ? r11.z : r11.x;
        const float v111 = k ? r11.w : r11.y;

        // stage 1: along w
        const float a0 = v000 + v001, a1 = v000 - v001;
        const float a2 = v010 + v011, a3 = v010 - v011;
        const float a4 = v100 + v101, a5 = v100 - v101;
        const float a6 = v110 + v111, a7 = v110 - v111;
        // stage 2: along h
        const float b0 = a0 + a2, b1 = a1 + a3, b2 = a0 - a2, b3 = a1 - a3;
        const float b4 = a4 + a6, b5 = a5 + a7, b6 = a4 - a6, b7 = a5 - a7;
        // stage 3: along t; filter f bits = (t_flip<<2)|(h_flip<<1)|w_flip
        float r[8];
        r[0] = (b0 + b4) * HAAR_SCALE;  // 000
        r[1] = (b1 + b5) * HAAR_SCALE;  // 001 w
        r[2] = (b2 + b6) * HAAR_SCALE;  // 010 h
        r[3] = (b3 + b7) * HAAR_SCALE;  // 011 hw
        r[4] = (b0 - b4) * HAAR_SCALE;  // 100 t
        r[5] = (b1 - b5) * HAAR_SCALE;  // 101 tw
        r[6] = (b2 - b6) * HAAR_SCALE;  // 110 th
        r[7] = (b3 - b7) * HAAR_SCALE;  // 111 thw
        #pragma unroll
        for (int f = 0; f < 8; f++) {
            if (k == 0) o[f].x = r[f]; else o[f].y = r[f];
        }
    }

    const int  b  = bc / 3;
    const int  c  = bc - 3 * b;
    const size_t OUT_FRAME = (size_t)OUT_H * OUT_W;   // 65536
    const size_t spatial = (size_t)t * OUT_FRAME + (size_t)h * OUT_W + (size_t)wp * 2;

    #pragma unroll
    for (int f = 0; f < 8; f++) {
        const size_t ch = (size_t)(b * 24 + f * 3 + c);
        __stcs((float2*)(out + ch * OUT_T * OUT_FRAME + spatial), o[f]);
    }
}

extern "C" void kernel_launch(void* const* d_in, const int* in_sizes, int n_in,
                              void* d_out, int out_size)
{
    const float* x = (const float*)d_in[0];
    float* out = (float*)d_out;
    // total threads = NBC * OUT_T * OUT_H * WP = 6*17*256*128 = 3,342,336
    const int total = NBC * OUT_T * OUT_H * WP;
    const int blocks = (total + TPB - 1) / TPB;
    haar3d_kernel<<<blocks, TPB>>>(x, out);
}